// round 12
// baseline (speedup 1.0000x reference)
#include <cuda_runtime.h>
#include <math.h>

#define IMG_H 2048
#define IMG_W 2048
#define HW (IMG_H * IMG_W)
#define THRESH 10.0f

// 180 / 3.14159 (reference constant, NOT pi)
#define RAD2DEG_D 57.29582790879777437539

// Octant boundary tangents (see R7 derivation)
#define T1_POS 0.41421317376f
#define T2_POS 2.41420677f
#define T1_NEG 0.41421628f
#define T2_NEG 2.41422489f
#define BAND1 1.0e-3f
#define BAND2 6.0e-3f

__device__ __forceinline__ float ldz_g(const float* __restrict__ p, int Y, int X) {
    return (Y >= 0 && Y < IMG_H && X >= 0 && X < IMG_W) ? __ldg(p + Y * IMG_W + X) : 0.0f;
}

__device__ __forceinline__ float sqrt_approx(float x) {
    float r;
    asm("sqrt.approx.f32 %0, %1;" : "=f"(r) : "f"(x));
    return r;
}

// ---------------------------------------------------------------------------
// Exact (fp64) helpers reading the global blurred map (zero-padded).
// Integer-weight sums of fp32 are fp64-exact; identical math to prior rounds.
// ---------------------------------------------------------------------------
__device__ __noinline__ void sobel_exact_g(const float* __restrict__ blurred,
                                           int Y, int X,
                                           double& ogx, double& ogy, double& omag) {
    double gxs = 0.0, gys = 0.0, mg = 0.0;
#pragma unroll
    for (int c = 0; c < 3; c++) {
        const float* __restrict__ p = blurred + c * HW;
        const double a  = ldz_g(p, Y - 1, X - 1);
        const double b  = ldz_g(p, Y - 1, X    );
        const double cc = ldz_g(p, Y - 1, X + 1);
        const double d  = ldz_g(p, Y,     X - 1);
        const double e  = ldz_g(p, Y,     X + 1);
        const double f  = ldz_g(p, Y + 1, X - 1);
        const double g  = ldz_g(p, Y + 1, X    );
        const double h  = ldz_g(p, Y + 1, X + 1);
        const double gx = (a - cc) + 2.0 * (d - e) + (f - h);
        const double gy = (a + 2.0 * b + cc) - (f + 2.0 * g + h);
        gxs += gx; gys += gy;
        mg += sqrt(gx * gx + gy * gy);
    }
    ogx = gxs; ogy = gys; omag = mg;
}

__device__ __noinline__ int orient_k_exact_g(const float* __restrict__ blurred,
                                             int Y, int X) {
    double gx, gy, m;
    sobel_exact_g(blurred, Y, X, gx, gy, m);
    const double orient = atan2(gy, gx) * RAD2DEG_D + 180.0;
    return (int)rint(orient / 45.0);
}

__device__ __noinline__ double mag_exact_g(const float* __restrict__ blurred,
                                           int Y, int X) {
    if (X < 0 || X >= IMG_W || Y < 0 || Y >= IMG_H) return 0.0;
    double gx, gy, m;
    sobel_exact_g(blurred, Y, X, gx, gy, m);
    return m;
}

// Packed direction tables (value+1 in nibbles, dir d at nibble 4d)
#define DX_PACK 0x21000122u
#define DY_PACK 0x00012221u
__device__ __forceinline__ int unpack_d(unsigned pack, int d) {
    return (int)((pack >> (4 * d)) & 0xFu) - 1;
}

// Octant quantization with risk detection; exact fallback reads global blurred.
__device__ __forceinline__ int orient_k_fast_g(const float* __restrict__ blurred,
                                               float sgx, float sgy, int Y, int X) {
    const float ax = fabsf(sgx), ay = fabsf(sgy);
    const bool gxneg = sgx < 0.0f;
    const bool gypos = (__float_as_int(sgy) >= 0);
    int kq;
    bool risky;
    if (!gxneg) {
        const float lo = T1_POS * ax, hi = T2_POS * ax;
        risky = (fabsf(ay - lo) <= BAND1 * ax) || (fabsf(ay - hi) <= BAND2 * ax);
        if (ay < lo)      kq = 4;
        else if (ay < hi) kq = gypos ? 5 : 3;
        else              kq = gypos ? 6 : 2;
    } else {
        const float lo = T1_NEG * ax, hi = T2_NEG * ax;
        risky = (fabsf(ay - lo) <= BAND1 * ax) || (fabsf(ay - hi) <= BAND2 * ax) ||
                (ay <= 1e-3f * ax);
        if (ay < lo)      kq = gypos ? 8 : 0;
        else if (ay < hi) kq = gypos ? 7 : 1;
        else              kq = gypos ? 6 : 2;
    }
    if (risky) kq = orient_k_exact_g(blurred, Y, X);
    return kq;
}

// ---------------------------------------------------------------------------
// K1: horizontal 5-tap blur. tasks = 3 * 2048 * 512 (4 px/thread).
// hbuf[c][y][x] = h-sum centered at (y, x), zero-padded in x.
// ---------------------------------------------------------------------------
__global__ void __launch_bounds__(256) k_hblur(const float* __restrict__ img,
                                               const float* __restrict__ g5,
                                               float* __restrict__ hbuf) {
    const int t = blockIdx.x * 256 + threadIdx.x;
    const int c = t >> 20;             // 2048*512 = 2^20
    const int rem = t & 0xFFFFF;
    const int y = rem >> 9;
    const int g = rem & 511;

    const float g0 = __ldg(g5 + 0), g1 = __ldg(g5 + 1), g2 = __ldg(g5 + 2),
                g3 = __ldg(g5 + 3), g4 = __ldg(g5 + 4);

    const float* __restrict__ row = img + c * HW + y * IMG_W;
    float4 o;
    if (g > 0 && g < 511) {
        const float4 A = __ldg((const float4*)(row + 4 * g - 4));
        const float4 B = __ldg((const float4*)(row + 4 * g));
        const float4 C = __ldg((const float4*)(row + 4 * g + 4));
        const float w[12] = {A.x, A.y, A.z, A.w, B.x, B.y, B.z, B.w,
                             C.x, C.y, C.z, C.w};
        float o4[4];
#pragma unroll
        for (int i = 0; i < 4; i++) {
            float v = g2 * w[i + 4];
            v = fmaf(g0, w[i + 2], v);
            v = fmaf(g1, w[i + 3], v);
            v = fmaf(g3, w[i + 5], v);
            v = fmaf(g4, w[i + 6], v);
            o4[i] = v;
        }
        o = make_float4(o4[0], o4[1], o4[2], o4[3]);
    } else {
        float o4[4];
#pragma unroll
        for (int i = 0; i < 4; i++) {
            const int X = 4 * g + i;
            float v = g2 * __ldg(row + X);
            v = fmaf(g0, (X >= 2) ? __ldg(row + X - 2) : 0.0f, v);
            v = fmaf(g1, (X >= 1) ? __ldg(row + X - 1) : 0.0f, v);
            v = fmaf(g3, (X + 1 < IMG_W) ? __ldg(row + X + 1) : 0.0f, v);
            v = fmaf(g4, (X + 2 < IMG_W) ? __ldg(row + X + 2) : 0.0f, v);
            o4[i] = v;
        }
        o = make_float4(o4[0], o4[1], o4[2], o4[3]);
    }
    *(float4*)&hbuf[c * HW + y * IMG_W + 4 * g] = o;
}

// ---------------------------------------------------------------------------
// K2: vertical 5-tap blur. tasks = 3 * 2048 * 512.
// ---------------------------------------------------------------------------
__global__ void __launch_bounds__(256) k_vblur(const float* __restrict__ hbuf,
                                               const float* __restrict__ g5,
                                               float* __restrict__ blurred) {
    const int t = blockIdx.x * 256 + threadIdx.x;
    const int c = t >> 20;
    const int rem = t & 0xFFFFF;
    const int y = rem >> 9;
    const int g = rem & 511;
    const int col = 4 * g;

    const float g0 = __ldg(g5 + 0), g1 = __ldg(g5 + 1), g2 = __ldg(g5 + 2),
                g3 = __ldg(g5 + 3), g4 = __ldg(g5 + 4);

    const float* __restrict__ base = hbuf + c * HW + col;
    const float4 z4 = make_float4(0.f, 0.f, 0.f, 0.f);
    float4 h[5];
#pragma unroll
    for (int j = 0; j < 5; j++) {
        const int ry = y - 2 + j;
        h[j] = (ry >= 0 && ry < IMG_H) ? __ldg((const float4*)(base + ry * IMG_W)) : z4;
    }
    float4 o;
    o.x = fmaf(g4, h[4].x, fmaf(g3, h[3].x, fmaf(g2, h[2].x, fmaf(g1, h[1].x, g0 * h[0].x))));
    o.y = fmaf(g4, h[4].y, fmaf(g3, h[3].y, fmaf(g2, h[2].y, fmaf(g1, h[1].y, g0 * h[0].y))));
    o.z = fmaf(g4, h[4].z, fmaf(g3, h[3].z, fmaf(g2, h[2].z, fmaf(g1, h[1].z, g0 * h[0].z))));
    o.w = fmaf(g4, h[4].w, fmaf(g3, h[3].w, fmaf(g2, h[2].w, fmaf(g1, h[1].w, g0 * h[0].w))));
    *(float4*)&blurred[c * HW + y * IMG_W + col] = o;
}

// ---------------------------------------------------------------------------
// K3: sobel -> mag, quantized orientation (*45), early threshold.
// tasks = 2048 * 512.
// ---------------------------------------------------------------------------
__global__ void __launch_bounds__(256) k_sobel(const float* __restrict__ blurred,
                                               float* __restrict__ mag_out,
                                               float* __restrict__ orient_out,
                                               float* __restrict__ early_out) {
    const int t = blockIdx.x * 256 + threadIdx.x;
    const int y = t >> 9;
    const int g = t & 511;

    float m[4]  = {0.f, 0.f, 0.f, 0.f};
    float sx[4] = {0.f, 0.f, 0.f, 0.f};
    float sy[4] = {0.f, 0.f, 0.f, 0.f};

    if (y >= 1 && y < IMG_H - 1 && g > 0 && g < 511) {
#pragma unroll
        for (int c = 0; c < 3; c++) {
            const float* __restrict__ p = blurred + c * HW + 4 * g - 4;
            const float* r0 = p + (y - 1) * IMG_W;
            const float* r1 = p + y * IMG_W;
            const float* r2 = p + (y + 1) * IMG_W;
            const float4 A0 = __ldg((const float4*)r0);
            const float4 B0 = __ldg((const float4*)(r0 + 4));
            const float4 C0 = __ldg((const float4*)(r0 + 8));
            const float4 A1 = __ldg((const float4*)r1);
            const float4 B1 = __ldg((const float4*)(r1 + 4));
            const float4 C1 = __ldg((const float4*)(r1 + 8));
            const float4 A2 = __ldg((const float4*)r2);
            const float4 B2 = __ldg((const float4*)(r2 + 4));
            const float4 C2 = __ldg((const float4*)(r2 + 8));
            const float w0[12] = {A0.x, A0.y, A0.z, A0.w, B0.x, B0.y, B0.z, B0.w,
                                  C0.x, C0.y, C0.z, C0.w};
            const float w1[12] = {A1.x, A1.y, A1.z, A1.w, B1.x, B1.y, B1.z, B1.w,
                                  C1.x, C1.y, C1.z, C1.w};
            const float w2[12] = {A2.x, A2.y, A2.z, A2.w, B2.x, B2.y, B2.z, B2.w,
                                  C2.x, C2.y, C2.z, C2.w};
#pragma unroll
            for (int i = 0; i < 4; i++) {
                const float a  = w0[i + 3], b = w0[i + 4], cc = w0[i + 5];
                const float d  = w1[i + 3], e = w1[i + 5];
                const float f  = w2[i + 3], gg = w2[i + 4], h = w2[i + 5];
                const float gx = (a - cc) + 2.0f * (d - e) + (f - h);
                const float gy = (a + 2.0f * b + cc) - (f + 2.0f * gg + h);
                m[i] += sqrt_approx(fmaf(gx, gx, gy * gy));
                sx[i] += gx;
                sy[i] += gy;
            }
        }
    } else {
#pragma unroll
        for (int c = 0; c < 3; c++) {
            const float* __restrict__ p = blurred + c * HW;
#pragma unroll
            for (int i = 0; i < 4; i++) {
                const int X = 4 * g + i;
                const float a  = ldz_g(p, y - 1, X - 1);
                const float b  = ldz_g(p, y - 1, X    );
                const float cc = ldz_g(p, y - 1, X + 1);
                const float d  = ldz_g(p, y,     X - 1);
                const float e  = ldz_g(p, y,     X + 1);
                const float f  = ldz_g(p, y + 1, X - 1);
                const float gg = ldz_g(p, y + 1, X    );
                const float h  = ldz_g(p, y + 1, X + 1);
                const float gx = (a - cc) + 2.0f * (d - e) + (f - h);
                const float gy = (a + 2.0f * b + cc) - (f + 2.0f * gg + h);
                m[i] += sqrt_approx(fmaf(gx, gx, gy * gy));
                sx[i] += gx;
                sy[i] += gy;
            }
        }
    }

    float vo[4], ve[4];
#pragma unroll
    for (int i = 0; i < 4; i++) {
        const int kq = orient_k_fast_g(blurred, sx[i], sy[i], y, 4 * g + i);
        vo[i] = 45.0f * (float)kq;
        ve[i] = (m[i] < THRESH) ? 0.0f : m[i];
    }
    const int idx = y * IMG_W + 4 * g;
    *(float4*)&mag_out[idx]    = make_float4(m[0], m[1], m[2], m[3]);
    *(float4*)&orient_out[idx] = make_float4(vo[0], vo[1], vo[2], vo[3]);
    *(float4*)&early_out[idx]  = make_float4(ve[0], ve[1], ve[2], ve[3]);
}

// ---------------------------------------------------------------------------
// K4: NMS + threshold. tasks = 2048 * 512.
// ---------------------------------------------------------------------------
__global__ void __launch_bounds__(256) k_nms(const float* __restrict__ mag,
                                             const float* __restrict__ orient,
                                             const float* __restrict__ blurred,
                                             float* __restrict__ thin_out,
                                             float* __restrict__ thresh_out) {
    const int t = blockIdx.x * 256 + threadIdx.x;
    const int y = t >> 9;
    const int g = t & 511;

    float vt[4], vh[4];

    if (y >= 1 && y < IMG_H - 1 && g > 0 && g < 511) {
        const float* p = mag + 4 * g - 4;
        const float4 A0 = __ldg((const float4*)(p + (y - 1) * IMG_W));
        const float4 B0 = __ldg((const float4*)(p + (y - 1) * IMG_W + 4));
        const float4 C0 = __ldg((const float4*)(p + (y - 1) * IMG_W + 8));
        const float4 A1 = __ldg((const float4*)(p + y * IMG_W));
        const float4 B1 = __ldg((const float4*)(p + y * IMG_W + 4));
        const float4 C1 = __ldg((const float4*)(p + y * IMG_W + 8));
        const float4 A2 = __ldg((const float4*)(p + (y + 1) * IMG_W));
        const float4 B2 = __ldg((const float4*)(p + (y + 1) * IMG_W + 4));
        const float4 C2 = __ldg((const float4*)(p + (y + 1) * IMG_W + 8));
        const float w[3][12] = {
            {A0.x, A0.y, A0.z, A0.w, B0.x, B0.y, B0.z, B0.w, C0.x, C0.y, C0.z, C0.w},
            {A1.x, A1.y, A1.z, A1.w, B1.x, B1.y, B1.z, B1.w, C1.x, C1.y, C1.z, C1.w},
            {A2.x, A2.y, A2.z, A2.w, B2.x, B2.y, B2.z, B2.w, C2.x, C2.y, C2.z, C2.w}};
        const float4 ov = __ldg((const float4*)(orient + y * IMG_W + 4 * g));
        const float o4[4] = {ov.x, ov.y, ov.z, ov.w};
#pragma unroll
        for (int i = 0; i < 4; i++) {
            const float mm = w[1][i + 4];
            const int kq  = (int)rintf(o4[i] * (1.0f / 45.0f));
            const int ip  = kq & 7;
            const int in_ = (kq + 4) & 7;
            const int pdy = unpack_d(DY_PACK, ip),  pdx = unpack_d(DX_PACK, ip);
            const int ndy = unpack_d(DY_PACK, in_), ndx = unpack_d(DX_PACK, in_);

            const float npos = w[1 + pdy][i + 4 + pdx];
            const float nneg = w[1 + ndy][i + 4 + ndx];
            const float sel_min = fminf(mm - npos, mm - nneg);

            bool is_max;
            const float eps = 4e-6f * fmaxf(mm, 1.0f);
            if (fabsf(sel_min) > eps) {
                is_max = sel_min > 0.0f;
            } else {
                const int X = 4 * g + i;
                const double md = mag_exact_g(blurred, y, X);
                const double dp = md - mag_exact_g(blurred, y + pdy, X + pdx);
                const double dn = md - mag_exact_g(blurred, y + ndy, X + ndx);
                is_max = fmin(dp, dn) > 0.0;
            }
            const float thin = is_max ? mm : 0.0f;
            vt[i] = thin;
            vh[i] = (thin < THRESH) ? 0.0f : thin;
        }
    } else {
#pragma unroll
        for (int i = 0; i < 4; i++) {
            const int X = 4 * g + i;
            const float mm = __ldg(mag + y * IMG_W + X);
            const int kq  = (int)rintf(__ldg(orient + y * IMG_W + X) * (1.0f / 45.0f));
            const int ip  = kq & 7;
            const int in_ = (kq + 4) & 7;
            const int pdy = unpack_d(DY_PACK, ip),  pdx = unpack_d(DX_PACK, ip);
            const int ndy = unpack_d(DY_PACK, in_), ndx = unpack_d(DX_PACK, in_);

            const float npos = ldz_g(mag, y + pdy, X + pdx);
            const float nneg = ldz_g(mag, y + ndy, X + ndx);
            const float sel_min = fminf(mm - npos, mm - nneg);

            bool is_max;
            const float eps = 4e-6f * fmaxf(mm, 1.0f);
            if (fabsf(sel_min) > eps) {
                is_max = sel_min > 0.0f;
            } else {
                const double md = mag_exact_g(blurred, y, X);
                const double dp = md - mag_exact_g(blurred, y + pdy, X + pdx);
                const double dn = md - mag_exact_g(blurred, y + ndy, X + ndx);
                is_max = fmin(dp, dn) > 0.0;
            }
            const float thin = is_max ? mm : 0.0f;
            vt[i] = thin;
            vh[i] = (thin < THRESH) ? 0.0f : thin;
        }
    }

    const int idx = y * IMG_W + 4 * g;
    *(float4*)&thin_out[idx]   = make_float4(vt[0], vt[1], vt[2], vt[3]);
    *(float4*)&thresh_out[idx] = make_float4(vh[0], vh[1], vh[2], vh[3]);
}

// ---------------------------------------------------------------------------
// Output layout (concatenated reference tuple, fp32):
//   [0,3HW) blurred | [3HW,4HW) mag | [4HW,5HW) orient | [5HW,6HW) thin
//   [6HW,7HW) thresholded | [7HW,8HW) early
// Scratch: hbuf lives in [5HW,8HW) (thin/thresh/early regions) — dead until
// K4/K3 overwrite them, after K2 has consumed hbuf.
// ---------------------------------------------------------------------------
extern "C" void kernel_launch(void* const* d_in, const int* in_sizes, int n_in,
                              void* d_out, int out_size) {
    const float* img  = (const float*)d_in[0];
    const float* gh_w = (const float*)d_in[1];

    float* out      = (float*)d_out;
    float* blurred  = out;
    float* mag      = out + 3 * (size_t)HW;
    float* orient   = out + 4 * (size_t)HW;
    float* thin     = out + 5 * (size_t)HW;
    float* threshed = out + 6 * (size_t)HW;
    float* early    = out + 7 * (size_t)HW;
    float* hbuf     = out + 5 * (size_t)HW;   // scratch (3 planes)

    k_hblur<<<12288, 256>>>(img, gh_w, hbuf);
    k_vblur<<<12288, 256>>>(hbuf, gh_w, blurred);
    k_sobel<<<4096, 256>>>(blurred, mag, orient, early);
    k_nms<<<4096, 256>>>(mag, orient, blurred, thin, threshed);
}

// round 13
// speedup vs baseline: 1.0294x; 1.0294x over previous
#include <cuda_runtime.h>
#include <math.h>

#define IMG_H 2048
#define IMG_W 2048
#define HW (IMG_H * IMG_W)
#define THRESH 10.0f

// 180 / 3.14159 (reference constant, NOT pi)
#define RAD2DEG_D 57.29582790879777437539

// Octant boundary tangents (see R7 derivation)
#define T1_POS 0.41421317376f
#define T2_POS 2.41420677f
#define T1_NEG 0.41421628f
#define T2_NEG 2.41422489f
#define BAND1 1.0e-3f
#define BAND2 6.0e-3f

__device__ __forceinline__ float ldz_g(const float* __restrict__ p, int Y, int X) {
    return (Y >= 0 && Y < IMG_H && X >= 0 && X < IMG_W) ? __ldg(p + Y * IMG_W + X) : 0.0f;
}

__device__ __forceinline__ float sqrt_approx(float x) {
    float r;
    asm("sqrt.approx.f32 %0, %1;" : "=f"(r) : "f"(x));
    return r;
}

// ---------------------------------------------------------------------------
// Exact (fp64) helpers reading the global blurred map (zero-padded).
// ---------------------------------------------------------------------------
__device__ __noinline__ void sobel_exact_g(const float* __restrict__ blurred,
                                           int Y, int X,
                                           double& ogx, double& ogy, double& omag) {
    double gxs = 0.0, gys = 0.0, mg = 0.0;
#pragma unroll
    for (int c = 0; c < 3; c++) {
        const float* __restrict__ p = blurred + c * HW;
        const double a  = ldz_g(p, Y - 1, X - 1);
        const double b  = ldz_g(p, Y - 1, X    );
        const double cc = ldz_g(p, Y - 1, X + 1);
        const double d  = ldz_g(p, Y,     X - 1);
        const double e  = ldz_g(p, Y,     X + 1);
        const double f  = ldz_g(p, Y + 1, X - 1);
        const double g  = ldz_g(p, Y + 1, X    );
        const double h  = ldz_g(p, Y + 1, X + 1);
        const double gx = (a - cc) + 2.0 * (d - e) + (f - h);
        const double gy = (a + 2.0 * b + cc) - (f + 2.0 * g + h);
        gxs += gx; gys += gy;
        mg += sqrt(gx * gx + gy * gy);
    }
    ogx = gxs; ogy = gys; omag = mg;
}

__device__ __noinline__ int orient_k_exact_g(const float* __restrict__ blurred,
                                             int Y, int X) {
    double gx, gy, m;
    sobel_exact_g(blurred, Y, X, gx, gy, m);
    const double orient = atan2(gy, gx) * RAD2DEG_D + 180.0;
    return (int)rint(orient / 45.0);
}

__device__ __noinline__ double mag_exact_g(const float* __restrict__ blurred,
                                           int Y, int X) {
    if (X < 0 || X >= IMG_W || Y < 0 || Y >= IMG_H) return 0.0;
    double gx, gy, m;
    sobel_exact_g(blurred, Y, X, gx, gy, m);
    return m;
}

// Packed direction tables (value+1 in nibbles, dir d at nibble 4d)
#define DX_PACK 0x21000122u
#define DY_PACK 0x00012221u
__device__ __forceinline__ int unpack_d(unsigned pack, int d) {
    return (int)((pack >> (4 * d)) & 0xFu) - 1;
}

// ---------------------------------------------------------------------------
// K1: horizontal 5-tap blur. 3 * 2^20 tasks (4 px/thread).
// ---------------------------------------------------------------------------
__global__ void __launch_bounds__(256, 8) k_hblur(const float* __restrict__ img,
                                                  const float* __restrict__ g5,
                                                  float* __restrict__ hbuf) {
    const int t = blockIdx.x * 256 + threadIdx.x;
    const int c = t >> 20;
    const int rem = t & 0xFFFFF;
    const int y = rem >> 9;
    const int g = rem & 511;

    const float g0 = __ldg(g5 + 0), g1 = __ldg(g5 + 1), g2 = __ldg(g5 + 2),
                g3 = __ldg(g5 + 3), g4 = __ldg(g5 + 4);

    const float* __restrict__ row = img + c * HW + y * IMG_W;
    float o4[4];
    if (g > 0 && g < 511) {
        const float4 A = __ldg((const float4*)(row + 4 * g - 4));
        const float4 B = __ldg((const float4*)(row + 4 * g));
        const float4 C = __ldg((const float4*)(row + 4 * g + 4));
        const float w[12] = {A.x, A.y, A.z, A.w, B.x, B.y, B.z, B.w,
                             C.x, C.y, C.z, C.w};
#pragma unroll
        for (int i = 0; i < 4; i++) {
            float v = g2 * w[i + 4];
            v = fmaf(g0, w[i + 2], v);
            v = fmaf(g1, w[i + 3], v);
            v = fmaf(g3, w[i + 5], v);
            v = fmaf(g4, w[i + 6], v);
            o4[i] = v;
        }
    } else {
#pragma unroll
        for (int i = 0; i < 4; i++) {
            const int X = 4 * g + i;
            float v = g2 * __ldg(row + X);
            v = fmaf(g0, (X >= 2) ? __ldg(row + X - 2) : 0.0f, v);
            v = fmaf(g1, (X >= 1) ? __ldg(row + X - 1) : 0.0f, v);
            v = fmaf(g3, (X + 1 < IMG_W) ? __ldg(row + X + 1) : 0.0f, v);
            v = fmaf(g4, (X + 2 < IMG_W) ? __ldg(row + X + 2) : 0.0f, v);
            o4[i] = v;
        }
    }
    *(float4*)&hbuf[c * HW + y * IMG_W + 4 * g] = make_float4(o4[0], o4[1], o4[2], o4[3]);
}

// ---------------------------------------------------------------------------
// K2: vertical 5-tap blur. 3 * 2^20 tasks.
// ---------------------------------------------------------------------------
__global__ void __launch_bounds__(256, 8) k_vblur(const float* __restrict__ hbuf,
                                                  const float* __restrict__ g5,
                                                  float* __restrict__ blurred) {
    const int t = blockIdx.x * 256 + threadIdx.x;
    const int c = t >> 20;
    const int rem = t & 0xFFFFF;
    const int y = rem >> 9;
    const int g = rem & 511;
    const int col = 4 * g;

    const float g0 = __ldg(g5 + 0), g1 = __ldg(g5 + 1), g2 = __ldg(g5 + 2),
                g3 = __ldg(g5 + 3), g4 = __ldg(g5 + 4);

    const float* __restrict__ base = hbuf + c * HW + col;
    const float4 z4 = make_float4(0.f, 0.f, 0.f, 0.f);
    float4 h[5];
#pragma unroll
    for (int j = 0; j < 5; j++) {
        const int ry = y - 2 + j;
        h[j] = (ry >= 0 && ry < IMG_H) ? __ldg((const float4*)(base + ry * IMG_W)) : z4;
    }
    float4 o;
    o.x = fmaf(g4, h[4].x, fmaf(g3, h[3].x, fmaf(g2, h[2].x, fmaf(g1, h[1].x, g0 * h[0].x))));
    o.y = fmaf(g4, h[4].y, fmaf(g3, h[3].y, fmaf(g2, h[2].y, fmaf(g1, h[1].y, g0 * h[0].y))));
    o.z = fmaf(g4, h[4].z, fmaf(g3, h[3].z, fmaf(g2, h[2].z, fmaf(g1, h[1].z, g0 * h[0].z))));
    o.w = fmaf(g4, h[4].w, fmaf(g3, h[3].w, fmaf(g2, h[2].w, fmaf(g1, h[1].w, g0 * h[0].w))));
    *(float4*)&blurred[c * HW + y * IMG_W + col] = o;
}

// ---------------------------------------------------------------------------
// K3: sobel -> mag, quantized orientation (*45), early threshold. 2^20 tasks.
// Only 6 scalars/row/channel live; fp64 rescue deferred behind riskyMask.
// ---------------------------------------------------------------------------
__global__ void __launch_bounds__(256, 5) k_sobel(const float* __restrict__ blurred,
                                                  float* __restrict__ mag_out,
                                                  float* __restrict__ orient_out,
                                                  float* __restrict__ early_out) {
    const int t = blockIdx.x * 256 + threadIdx.x;
    const int y = t >> 9;
    const int g = t & 511;

    float m[4]  = {0.f, 0.f, 0.f, 0.f};
    float sx[4] = {0.f, 0.f, 0.f, 0.f};
    float sy[4] = {0.f, 0.f, 0.f, 0.f};

    if (y >= 1 && y < IMG_H - 1 && g > 0 && g < 511) {
#pragma unroll
        for (int c = 0; c < 3; c++) {
            const float* __restrict__ p = blurred + c * HW + 4 * g;
            float v0[6], v1[6], v2[6];
            {
                const float* r0 = p + (y - 1) * IMG_W;
                const float4 B = __ldg((const float4*)r0);
                v0[0] = __ldg(r0 - 1);
                v0[1] = B.x; v0[2] = B.y; v0[3] = B.z; v0[4] = B.w;
                v0[5] = __ldg(r0 + 4);
            }
            {
                const float* r1 = p + y * IMG_W;
                const float4 B = __ldg((const float4*)r1);
                v1[0] = __ldg(r1 - 1);
                v1[1] = B.x; v1[2] = B.y; v1[3] = B.z; v1[4] = B.w;
                v1[5] = __ldg(r1 + 4);
            }
            {
                const float* r2 = p + (y + 1) * IMG_W;
                const float4 B = __ldg((const float4*)r2);
                v2[0] = __ldg(r2 - 1);
                v2[1] = B.x; v2[2] = B.y; v2[3] = B.z; v2[4] = B.w;
                v2[5] = __ldg(r2 + 4);
            }
#pragma unroll
            for (int i = 0; i < 4; i++) {
                const float a  = v0[i], b = v0[i + 1], cc = v0[i + 2];
                const float d  = v1[i], e = v1[i + 2];
                const float f  = v2[i], gg = v2[i + 1], h = v2[i + 2];
                const float gx = (a - cc) + 2.0f * (d - e) + (f - h);
                const float gy = (a + 2.0f * b + cc) - (f + 2.0f * gg + h);
                m[i] += sqrt_approx(fmaf(gx, gx, gy * gy));
                sx[i] += gx;
                sy[i] += gy;
            }
        }
    } else {
#pragma unroll
        for (int c = 0; c < 3; c++) {
            const float* __restrict__ p = blurred + c * HW;
#pragma unroll
            for (int i = 0; i < 4; i++) {
                const int X = 4 * g + i;
                const float a  = ldz_g(p, y - 1, X - 1);
                const float b  = ldz_g(p, y - 1, X    );
                const float cc = ldz_g(p, y - 1, X + 1);
                const float d  = ldz_g(p, y,     X - 1);
                const float e  = ldz_g(p, y,     X + 1);
                const float f  = ldz_g(p, y + 1, X - 1);
                const float gg = ldz_g(p, y + 1, X    );
                const float h  = ldz_g(p, y + 1, X + 1);
                const float gx = (a - cc) + 2.0f * (d - e) + (f - h);
                const float gy = (a + 2.0f * b + cc) - (f + 2.0f * gg + h);
                m[i] += sqrt_approx(fmaf(gx, gx, gy * gy));
                sx[i] += gx;
                sy[i] += gy;
            }
        }
    }

    // Fast octant quantization; collect risky pixels in a mask (rescue cold).
    float vo[4], ve[4];
    unsigned riskyMask = 0;
#pragma unroll
    for (int i = 0; i < 4; i++) {
        const float ax = fabsf(sx[i]), ay = fabsf(sy[i]);
        const bool gxneg = sx[i] < 0.0f;
        const bool gypos = (__float_as_int(sy[i]) >= 0);
        int kq;
        bool risky;
        if (!gxneg) {
            const float lo = T1_POS * ax, hi = T2_POS * ax;
            risky = (fabsf(ay - lo) <= BAND1 * ax) || (fabsf(ay - hi) <= BAND2 * ax);
            if (ay < lo)      kq = 4;
            else if (ay < hi) kq = gypos ? 5 : 3;
            else              kq = gypos ? 6 : 2;
        } else {
            const float lo = T1_NEG * ax, hi = T2_NEG * ax;
            risky = (fabsf(ay - lo) <= BAND1 * ax) || (fabsf(ay - hi) <= BAND2 * ax) ||
                    (ay <= 1e-3f * ax);
            if (ay < lo)      kq = gypos ? 8 : 0;
            else if (ay < hi) kq = gypos ? 7 : 1;
            else              kq = gypos ? 6 : 2;
        }
        if (risky) riskyMask |= (1u << i);
        vo[i] = 45.0f * (float)kq;
        ve[i] = (m[i] < THRESH) ? 0.0f : m[i];
    }
    if (riskyMask) {
#pragma unroll
        for (int i = 0; i < 4; i++) {
            if (riskyMask & (1u << i)) {
                vo[i] = 45.0f * (float)orient_k_exact_g(blurred, y, 4 * g + i);
            }
        }
    }

    const int idx = y * IMG_W + 4 * g;
    *(float4*)&mag_out[idx]    = make_float4(m[0], m[1], m[2], m[3]);
    *(float4*)&orient_out[idx] = make_float4(vo[0], vo[1], vo[2], vo[3]);
    *(float4*)&early_out[idx]  = make_float4(ve[0], ve[1], ve[2], ve[3]);
}

// ---------------------------------------------------------------------------
// K4: NMS + threshold. 2^20 tasks. Neighbors via direct scalar __ldg
// (L1-resident) — no dynamically-indexed register arrays.
// ---------------------------------------------------------------------------
__global__ void __launch_bounds__(256, 6) k_nms(const float* __restrict__ mag,
                                                const float* __restrict__ orient,
                                                const float* __restrict__ blurred,
                                                float* __restrict__ thin_out,
                                                float* __restrict__ thresh_out) {
    const int t = blockIdx.x * 256 + threadIdx.x;
    const int y = t >> 9;
    const int g = t & 511;
    const int idx = y * IMG_W + 4 * g;
    const bool interior = (y >= 1 && y < IMG_H - 1 && g > 0 && g < 511);

    const float4 mv = __ldg((const float4*)(mag + idx));
    const float4 ov = __ldg((const float4*)(orient + idx));
    const float m4[4] = {mv.x, mv.y, mv.z, mv.w};
    const float o4[4] = {ov.x, ov.y, ov.z, ov.w};

    float vt[4], vh[4];
    unsigned tieMask = 0;
    int pdyA[4], pdxA[4], ndyA[4], ndxA[4];

#pragma unroll
    for (int i = 0; i < 4; i++) {
        const int X = 4 * g + i;
        const float mm = m4[i];
        const int kq  = (int)rintf(o4[i] * (1.0f / 45.0f));
        const int ip  = kq & 7;
        const int in_ = (kq + 4) & 7;
        const int pdy = unpack_d(DY_PACK, ip),  pdx = unpack_d(DX_PACK, ip);
        const int ndy = unpack_d(DY_PACK, in_), ndx = unpack_d(DX_PACK, in_);
        pdyA[i] = pdy; pdxA[i] = pdx; ndyA[i] = ndy; ndxA[i] = ndx;

        float npos, nneg;
        if (interior) {
            npos = __ldg(mag + (y + pdy) * IMG_W + X + pdx);
            nneg = __ldg(mag + (y + ndy) * IMG_W + X + ndx);
        } else {
            npos = ldz_g(mag, y + pdy, X + pdx);
            nneg = ldz_g(mag, y + ndy, X + ndx);
        }
        const float sel_min = fminf(mm - npos, mm - nneg);
        const float eps = 4e-6f * fmaxf(mm, 1.0f);
        bool is_max = sel_min > 0.0f;
        if (fabsf(sel_min) <= eps) tieMask |= (1u << i);

        const float thin = is_max ? mm : 0.0f;
        vt[i] = thin;
        vh[i] = (thin < THRESH) ? 0.0f : thin;
    }

    if (tieMask) {
#pragma unroll
        for (int i = 0; i < 4; i++) {
            if (tieMask & (1u << i)) {
                const int X = 4 * g + i;
                const double md = mag_exact_g(blurred, y, X);
                const double dp = md - mag_exact_g(blurred, y + pdyA[i], X + pdxA[i]);
                const double dn = md - mag_exact_g(blurred, y + ndyA[i], X + ndxA[i]);
                const bool is_max = fmin(dp, dn) > 0.0;
                const float thin = is_max ? m4[i] : 0.0f;
                vt[i] = thin;
                vh[i] = (thin < THRESH) ? 0.0f : thin;
            }
        }
    }

    *(float4*)&thin_out[idx]   = make_float4(vt[0], vt[1], vt[2], vt[3]);
    *(float4*)&thresh_out[idx] = make_float4(vh[0], vh[1], vh[2], vh[3]);
}

// ---------------------------------------------------------------------------
// Output layout (concatenated reference tuple, fp32):
//   [0,3HW) blurred | [3HW,4HW) mag | [4HW,5HW) orient | [5HW,6HW) thin
//   [6HW,7HW) thresholded | [7HW,8HW) early
// Scratch: hbuf in [5HW,8HW) — consumed by K2 before K3/K4 overwrite it.
// ---------------------------------------------------------------------------
extern "C" void kernel_launch(void* const* d_in, const int* in_sizes, int n_in,
                              void* d_out, int out_size) {
    const float* img  = (const float*)d_in[0];
    const float* gh_w = (const float*)d_in[1];

    float* out      = (float*)d_out;
    float* blurred  = out;
    float* mag      = out + 3 * (size_t)HW;
    float* orient   = out + 4 * (size_t)HW;
    float* thin     = out + 5 * (size_t)HW;
    float* threshed = out + 6 * (size_t)HW;
    float* early    = out + 7 * (size_t)HW;
    float* hbuf     = out + 5 * (size_t)HW;   // scratch (3 planes)

    k_hblur<<<12288, 256>>>(img, gh_w, hbuf);
    k_vblur<<<12288, 256>>>(hbuf, gh_w, blurred);
    k_sobel<<<4096, 256>>>(blurred, mag, orient, early);
    k_nms<<<4096, 256>>>(mag, orient, blurred, thin, threshed);
}

// round 15
// speedup vs baseline: 1.0984x; 1.0671x over previous
#include <cuda_runtime.h>
#include <math.h>

#define IMG_H 2048
#define IMG_W 2048
#define HW (IMG_H * IMG_W)
#define THRESH 10.0f

// 180 / 3.14159 (reference constant, NOT pi)
#define RAD2DEG_D 57.29582790879777437539

// Octant boundary tangents (see R7 derivation)
#define T1_POS 0.41421317376f
#define T2_POS 2.41420677f
#define T1_NEG 0.41421628f
#define T2_NEG 2.41422489f
#define BAND1 1.0e-3f
#define BAND2 6.0e-3f

__device__ __forceinline__ float ldz_g(const float* __restrict__ p, int Y, int X) {
    return (Y >= 0 && Y < IMG_H && X >= 0 && X < IMG_W) ? __ldg(p + Y * IMG_W + X) : 0.0f;
}

__device__ __forceinline__ float sqrt_approx(float x) {
    float r;
    asm("sqrt.approx.f32 %0, %1;" : "=f"(r) : "f"(x));
    return r;
}

// ---------------------------------------------------------------------------
// Exact (fp64) helpers reading the global blurred map (zero-padded).
// ---------------------------------------------------------------------------
__device__ __noinline__ void sobel_exact_g(const float* __restrict__ blurred,
                                           int Y, int X,
                                           double& ogx, double& ogy, double& omag) {
    double gxs = 0.0, gys = 0.0, mg = 0.0;
#pragma unroll
    for (int c = 0; c < 3; c++) {
        const float* __restrict__ p = blurred + c * HW;
        const double a  = ldz_g(p, Y - 1, X - 1);
        const double b  = ldz_g(p, Y - 1, X    );
        const double cc = ldz_g(p, Y - 1, X + 1);
        const double d  = ldz_g(p, Y,     X - 1);
        const double e  = ldz_g(p, Y,     X + 1);
        const double f  = ldz_g(p, Y + 1, X - 1);
        const double g  = ldz_g(p, Y + 1, X    );
        const double h  = ldz_g(p, Y + 1, X + 1);
        const double gx = (a - cc) + 2.0 * (d - e) + (f - h);
        const double gy = (a + 2.0 * b + cc) - (f + 2.0 * g + h);
        gxs += gx; gys += gy;
        mg += sqrt(gx * gx + gy * gy);
    }
    ogx = gxs; ogy = gys; omag = mg;
}

__device__ __noinline__ int orient_k_exact_g(const float* __restrict__ blurred,
                                             int Y, int X) {
    double gx, gy, m;
    sobel_exact_g(blurred, Y, X, gx, gy, m);
    const double orient = atan2(gy, gx) * RAD2DEG_D + 180.0;
    return (int)rint(orient / 45.0);
}

__device__ __noinline__ double mag_exact_g(const float* __restrict__ blurred,
                                           int Y, int X) {
    if (X < 0 || X >= IMG_W || Y < 0 || Y >= IMG_H) return 0.0;
    double gx, gy, m;
    sobel_exact_g(blurred, Y, X, gx, gy, m);
    return m;
}

// Packed direction tables (value+1 in nibbles, dir d at nibble 4d)
#define DX_PACK 0x21000122u
#define DY_PACK 0x00012221u
__device__ __forceinline__ int unpack_d(unsigned pack, int d) {
    return (int)((pack >> (4 * d)) & 0xFu) - 1;
}

// ===========================================================================
// Kernel A: fused separable blur, one barrier.
//   hbuf[c][r][s]: h-sum at image (by0-2+r, bx0-2+s), r,s in 0..35.
// ===========================================================================
__device__ __forceinline__ void a1_task(float (*hbuf)[36][36],
                                        const float* __restrict__ img,
                                        float g0, float g1, float g2, float g3,
                                        float g4, int bx0, int by0, int t) {
    const int c = t / 324, rem = t - c * 324;
    const int r = rem / 9, g = rem - r * 9;
    const float* row = img + c * HW + (by0 - 2 + r) * IMG_W + (bx0 + 4 * g - 4);
    const float4 A = __ldg((const float4*)row);
    const float4 B = __ldg((const float4*)(row + 4));
    const float w[8] = {A.x, A.y, A.z, A.w, B.x, B.y, B.z, B.w};
    float o[4];
#pragma unroll
    for (int i = 0; i < 4; i++) {
        float v = g2 * w[i + 2];
        v = fmaf(g0, w[i],     v);
        v = fmaf(g1, w[i + 1], v);
        v = fmaf(g3, w[i + 3], v);
        v = fmaf(g4, w[i + 4], v);
        o[i] = v;
    }
    *(float4*)&hbuf[c][r][4 * g] = make_float4(o[0], o[1], o[2], o[3]);
}

__device__ __forceinline__ void a2_task(const float (*hbuf)[36][36],
                                        float* __restrict__ blurred,
                                        float g0, float g1, float g2, float g3,
                                        float g4, int bx0, int by0, int t) {
    const int c = t >> 8;               // 32 rows * 8 groups = 256
    const int rem = t & 255;
    const int y = rem >> 3, k = rem & 7;
    // output cols X = bx0+4k..+3 <-> hbuf cols s = 4k+2..4k+5
    float e[5][4];
#pragma unroll
    for (int j = 0; j < 5; j++) {
        const float4 q0 = *(const float4*)&hbuf[c][y + j][4 * k];
        const float4 q1 = *(const float4*)&hbuf[c][y + j][4 * k + 4];
        e[j][0] = q0.z; e[j][1] = q0.w; e[j][2] = q1.x; e[j][3] = q1.y;
    }
    float4 o;
    o.x = fmaf(g4, e[4][0], fmaf(g3, e[3][0], fmaf(g2, e[2][0], fmaf(g1, e[1][0], g0 * e[0][0]))));
    o.y = fmaf(g4, e[4][1], fmaf(g3, e[3][1], fmaf(g2, e[2][1], fmaf(g1, e[1][1], g0 * e[0][1]))));
    o.z = fmaf(g4, e[4][2], fmaf(g3, e[3][2], fmaf(g2, e[2][2], fmaf(g1, e[1][2], g0 * e[0][2]))));
    o.w = fmaf(g4, e[4][3], fmaf(g3, e[3][3], fmaf(g2, e[2][3], fmaf(g1, e[1][3], g0 * e[0][3]))));
    *(float4*)&blurred[c * HW + (by0 + y) * IMG_W + bx0 + 4 * k] = o;
}

__global__ void __launch_bounds__(256, 6)
k_blur(const float* __restrict__ img, const float* __restrict__ g5,
       float* __restrict__ blurred) {
    __shared__ float hbuf[3][36][36];
    const int tid = threadIdx.x;
    const int bx0 = blockIdx.x * 32;
    const int by0 = blockIdx.y * 32;

    const float g0 = __ldg(g5 + 0), g1 = __ldg(g5 + 1), g2 = __ldg(g5 + 2),
                g3 = __ldg(g5 + 3), g4 = __ldg(g5 + 4);

    const bool interior = (bx0 != 0) && (bx0 != IMG_W - 32) &&
                          (by0 != 0) && (by0 != IMG_H - 32);
    if (interior) {
        // A1: 3 x 36 x 9 = 972 tasks
        a1_task(hbuf, img, g0, g1, g2, g3, g4, bx0, by0, tid);
        a1_task(hbuf, img, g0, g1, g2, g3, g4, bx0, by0, tid + 256);
        a1_task(hbuf, img, g0, g1, g2, g3, g4, bx0, by0, tid + 512);
        if (tid < 204)
            a1_task(hbuf, img, g0, g1, g2, g3, g4, bx0, by0, tid + 768);
    } else {
        // scalar, zero-padded: 3 x 36 x 36 = 3888 tasks
        for (int t = tid; t < 3888; t += 256) {
            const int c = t / 1296, rem = t - c * 1296;
            const int r = rem / 36, s = rem - r * 36;
            const int Y = by0 - 2 + r, X = bx0 - 2 + s;
            const float* src = img + c * HW;
            float v = g2 * ldz_g(src, Y, X);
            v = fmaf(g0, ldz_g(src, Y, X - 2), v);
            v = fmaf(g1, ldz_g(src, Y, X - 1), v);
            v = fmaf(g3, ldz_g(src, Y, X + 1), v);
            v = fmaf(g4, ldz_g(src, Y, X + 2), v);
            hbuf[c][r][s] = v;
        }
    }
    __syncthreads();

    // A2: 3 x 32 x 8 = 768 tasks (h-rows outside the image are zero in hbuf,
    // matching zero padding; central rows always in-image).
    a2_task(hbuf, blurred, g0, g1, g2, g3, g4, bx0, by0, tid);
    a2_task(hbuf, blurred, g0, g1, g2, g3, g4, bx0, by0, tid + 256);
    a2_task(hbuf, blurred, g0, g1, g2, g3, g4, bx0, by0, tid + 512);
}

// ===========================================================================
// Kernel B: sobel + orientation + NMS, one barrier.
//   smag[r][col]: grad mag; col = X - bx0 + 8; r = Y - (by0-1).
// ===========================================================================
__device__ __forceinline__ void b_task(float (*smag)[44], signed char (*sk)[32],
                                       const float* __restrict__ blurred,
                                       int bx0, int by0, int t) {
    const int r = t / 10, g = t - 10 * r;   // r 0..33, g 0..9
    const int Y = by0 - 1 + r;
    const int X0 = bx0 - 4 + 4 * g;

    float m[4]  = {0.f, 0.f, 0.f, 0.f};
    float sx[4] = {0.f, 0.f, 0.f, 0.f};
    float sy[4] = {0.f, 0.f, 0.f, 0.f};
#pragma unroll
    for (int c = 0; c < 3; c++) {
        const float* __restrict__ p = blurred + c * HW + X0;
        float v0[6], v1[6], v2[6];
        {
            const float* rr = p + (Y - 1) * IMG_W;
            const float4 B = __ldg((const float4*)rr);
            v0[0] = __ldg(rr - 1);
            v0[1] = B.x; v0[2] = B.y; v0[3] = B.z; v0[4] = B.w;
            v0[5] = __ldg(rr + 4);
        }
        {
            const float* rr = p + Y * IMG_W;
            const float4 B = __ldg((const float4*)rr);
            v1[0] = __ldg(rr - 1);
            v1[1] = B.x; v1[2] = B.y; v1[3] = B.z; v1[4] = B.w;
            v1[5] = __ldg(rr + 4);
        }
        {
            const float* rr = p + (Y + 1) * IMG_W;
            const float4 B = __ldg((const float4*)rr);
            v2[0] = __ldg(rr - 1);
            v2[1] = B.x; v2[2] = B.y; v2[3] = B.z; v2[4] = B.w;
            v2[5] = __ldg(rr + 4);
        }
#pragma unroll
        for (int i = 0; i < 4; i++) {
            const float a  = v0[i], b = v0[i + 1], cc = v0[i + 2];
            const float d  = v1[i], e = v1[i + 2];
            const float f  = v2[i], gg = v2[i + 1], h = v2[i + 2];
            const float gx = (a - cc) + 2.0f * (d - e) + (f - h);
            const float gy = (a + 2.0f * b + cc) - (f + 2.0f * gg + h);
            m[i] += sqrt_approx(fmaf(gx, gx, gy * gy));
            sx[i] += gx;
            sy[i] += gy;
        }
    }
    *(float4*)&smag[r][4 * g + 4] = make_float4(m[0], m[1], m[2], m[3]);

    // orientation for central pixels only (r 1..32, g 1..8)
    if (r >= 1 && r < 33 && g >= 1 && g < 9) {
        unsigned riskyMask = 0;
        int kq4[4];
#pragma unroll
        for (int i = 0; i < 4; i++) {
            const float ax = fabsf(sx[i]), ay = fabsf(sy[i]);
            const bool gxneg = sx[i] < 0.0f;
            const bool gypos = (__float_as_int(sy[i]) >= 0);
            int kq;
            bool risky;
            if (!gxneg) {
                const float lo = T1_POS * ax, hi = T2_POS * ax;
                risky = (fabsf(ay - lo) <= BAND1 * ax) ||
                        (fabsf(ay - hi) <= BAND2 * ax);
                if (ay < lo)      kq = 4;
                else if (ay < hi) kq = gypos ? 5 : 3;
                else              kq = gypos ? 6 : 2;
            } else {
                const float lo = T1_NEG * ax, hi = T2_NEG * ax;
                risky = (fabsf(ay - lo) <= BAND1 * ax) ||
                        (fabsf(ay - hi) <= BAND2 * ax) ||
                        (ay <= 1e-3f * ax);
                if (ay < lo)      kq = gypos ? 8 : 0;
                else if (ay < hi) kq = gypos ? 7 : 1;
                else              kq = gypos ? 6 : 2;
            }
            if (risky) riskyMask |= (1u << i);
            kq4[i] = kq;
        }
        if (riskyMask) {
#pragma unroll
            for (int i = 0; i < 4; i++) {
                if (riskyMask & (1u << i))
                    kq4[i] = orient_k_exact_g(blurred, Y, X0 + i);
            }
        }
#pragma unroll
        for (int i = 0; i < 4; i++)
            sk[r - 1][4 * g - 4 + i] = (signed char)kq4[i];
    }
}

__global__ void __launch_bounds__(256, 5)
k_sobnms(const float* __restrict__ blurred,
         float* __restrict__ mag_out, float* __restrict__ orient_out,
         float* __restrict__ early_out, float* __restrict__ thin_out,
         float* __restrict__ thresh_out) {
    __shared__ float smag[34][44];
    __shared__ signed char sk[32][32];

    const int tid = threadIdx.x;
    const int bx0 = blockIdx.x * 32;
    const int by0 = blockIdx.y * 32;

    const bool interior = (bx0 != 0) && (bx0 != IMG_W - 32) &&
                          (by0 != 0) && (by0 != IMG_H - 32);

    if (interior) {
        // 34 x 10 = 340 tasks
        b_task(smag, sk, blurred, bx0, by0, tid);
        if (tid < 84) b_task(smag, sk, blurred, bx0, by0, tid + 256);
    } else {
        // scalar, zero-padded: 34 rows x 40 cols = 1360 tasks
        // col = s + 4; X = bx0 - 4 + s. Central pixels: s in [4,36), x = s-4.
        for (int t = tid; t < 1360; t += 256) {
            const int r = t / 40, s = t - 40 * r;
            const int Y = by0 - 1 + r, X = bx0 - 4 + s;
            float m = 0.0f, sgx = 0.0f, sgy = 0.0f;
            if (Y >= 0 && Y < IMG_H && X >= 0 && X < IMG_W) {
#pragma unroll
                for (int c = 0; c < 3; c++) {
                    const float* __restrict__ p = blurred + c * HW;
                    const float a  = ldz_g(p, Y - 1, X - 1);
                    const float b  = ldz_g(p, Y - 1, X    );
                    const float cc = ldz_g(p, Y - 1, X + 1);
                    const float d  = ldz_g(p, Y,     X - 1);
                    const float e  = ldz_g(p, Y,     X + 1);
                    const float f  = ldz_g(p, Y + 1, X - 1);
                    const float gg = ldz_g(p, Y + 1, X    );
                    const float h  = ldz_g(p, Y + 1, X + 1);
                    const float gx = (a - cc) + 2.0f * (d - e) + (f - h);
                    const float gy = (a + 2.0f * b + cc) - (f + 2.0f * gg + h);
                    m += sqrt_approx(fmaf(gx, gx, gy * gy));
                    sgx += gx;
                    sgy += gy;
                }
            }
            smag[r][s + 4] = m;
            if (r >= 1 && r < 33 && s >= 4 && s < 36) {
                const float ax = fabsf(sgx), ay = fabsf(sgy);
                const bool gxneg = sgx < 0.0f;
                const bool gypos = (__float_as_int(sgy) >= 0);
                int kq;
                bool risky;
                if (!gxneg) {
                    const float lo = T1_POS * ax, hi = T2_POS * ax;
                    risky = (fabsf(ay - lo) <= BAND1 * ax) ||
                            (fabsf(ay - hi) <= BAND2 * ax);
                    if (ay < lo)      kq = 4;
                    else if (ay < hi) kq = gypos ? 5 : 3;
                    else              kq = gypos ? 6 : 2;
                } else {
                    const float lo = T1_NEG * ax, hi = T2_NEG * ax;
                    risky = (fabsf(ay - lo) <= BAND1 * ax) ||
                            (fabsf(ay - hi) <= BAND2 * ax) ||
                            (ay <= 1e-3f * ax);
                    if (ay < lo)      kq = gypos ? 8 : 0;
                    else if (ay < hi) kq = gypos ? 7 : 1;
                    else              kq = gypos ? 6 : 2;
                }
                if (risky) kq = orient_k_exact_g(blurred, Y, X);
                sk[r - 1][s - 4] = (signed char)kq;
            }
        }
    }
    __syncthreads();

    // Stage C: NMS + 5 vector output stores (256 tasks exactly)
    {
        const int y = tid >> 3, g = tid & 7;
        const int Y = by0 + y;
        const int Xb = bx0 + 4 * g;
        float vm[4], vo[4], ve[4], vt[4], vh[4];
#pragma unroll
        for (int i = 0; i < 4; i++) {
            const int x = 4 * g + i;
            const float m = smag[y + 1][x + 8];
            const int kq  = (int)sk[y][x];

            vm[i] = m;
            vo[i] = 45.0f * (float)kq;
            ve[i] = (m < THRESH) ? 0.0f : m;

            const int ip  = kq & 7;
            const int in_ = (kq + 4) & 7;
            const int pdy = unpack_d(DY_PACK, ip),  pdx = unpack_d(DX_PACK, ip);
            const int ndy = unpack_d(DY_PACK, in_), ndx = unpack_d(DX_PACK, in_);

            const float npos = smag[y + 1 + pdy][x + 8 + pdx];
            const float nneg = smag[y + 1 + ndy][x + 8 + ndx];
            const float sel_min = fminf(m - npos, m - nneg);

            bool is_max;
            const float eps = 4e-6f * fmaxf(m, 1.0f);
            if (fabsf(sel_min) > eps) {
                is_max = sel_min > 0.0f;
            } else {
                const double md = mag_exact_g(blurred, Y, Xb + i);
                const double dp = md - mag_exact_g(blurred, Y + pdy, Xb + i + pdx);
                const double dn = md - mag_exact_g(blurred, Y + ndy, Xb + i + ndx);
                is_max = fmin(dp, dn) > 0.0;
            }

            const float thin = is_max ? m : 0.0f;
            vt[i] = thin;
            vh[i] = (thin < THRESH) ? 0.0f : thin;
        }
        const int idx = Y * IMG_W + Xb;
        *(float4*)&mag_out[idx]    = make_float4(vm[0], vm[1], vm[2], vm[3]);
        *(float4*)&orient_out[idx] = make_float4(vo[0], vo[1], vo[2], vo[3]);
        *(float4*)&early_out[idx]  = make_float4(ve[0], ve[1], ve[2], ve[3]);
        *(float4*)&thin_out[idx]   = make_float4(vt[0], vt[1], vt[2], vt[3]);
        *(float4*)&thresh_out[idx] = make_float4(vh[0], vh[1], vh[2], vh[3]);
    }
}

// ---------------------------------------------------------------------------
// Output layout (concatenated reference tuple, fp32):
//   [0,3HW) blurred | [3HW,4HW) mag | [4HW,5HW) orient | [5HW,6HW) thin
//   [6HW,7HW) thresholded | [7HW,8HW) early
// ---------------------------------------------------------------------------
extern "C" void kernel_launch(void* const* d_in, const int* in_sizes, int n_in,
                              void* d_out, int out_size) {
    const float* img  = (const float*)d_in[0];
    const float* gh_w = (const float*)d_in[1];

    float* out      = (float*)d_out;
    float* blurred  = out;
    float* mag      = out + 3 * (size_t)HW;
    float* orient   = out + 4 * (size_t)HW;
    float* thin     = out + 5 * (size_t)HW;
    float* threshed = out + 6 * (size_t)HW;
    float* early    = out + 7 * (size_t)HW;

    dim3 block(256, 1, 1);
    dim3 grid(IMG_W / 32, IMG_H / 32, 1);
    k_blur<<<grid, block>>>(img, gh_w, blurred);
    k_sobnms<<<grid, block>>>(blurred, mag, orient, early, thin, threshed);
}